// round 14
// baseline (speedup 1.0000x reference)
#include <cuda_runtime.h>
#include <cstdint>

// BERTEmbedding: out[b,l,:] = token_table[seq[b,l],:]
//                           + mean_{g<cnt}(genre_table[gids[seq[b,l],g],:])
//                           + pos_table[l,:]
//
// R14: token-row gathers via TMA bulk copies (cp.async.bulk) into smem —
// completely off the L1tex/LSU path. Per CTA: 64 tokens; threads 0..63 each
// issue one 512B row copy, all completing on one mbarrier (expect_tx=32KB).
// While copies fly, warps compute genre-mean + pos partials (L1-hot) into
// registers. After the barrier: add smem row, stream out with st.global.cs.

#define SEQ_L 200
#define MAX_G 8
#define NUM_TOKENS (256 * 200)
#define TOK_PER_CTA 64
#define BLOCK_THREADS 256
#define GRID_BLOCKS (NUM_TOKENS / TOK_PER_CTA)   // 800
#define ROW_BYTES 512
#define TILE_BYTES (TOK_PER_CTA * ROW_BYTES)     // 32768

__device__ __forceinline__ uint32_t smem_u32(const void* p) {
    uint32_t a;
    asm("{ .reg .u64 t; cvta.to.shared.u64 t, %1; cvt.u32.u64 %0, t; }"
        : "=r"(a) : "l"(p));
    return a;
}
__device__ __forceinline__ void stg_cs(float4* p, float4 v) {
    asm volatile("st.global.cs.v4.f32 [%0], {%1,%2,%3,%4};"
                 :: "l"(p), "f"(v.x), "f"(v.y), "f"(v.z), "f"(v.w) : "memory");
}

__global__ __launch_bounds__(BLOCK_THREADS) void bert_embed_kernel(
    const int* __restrict__ seq,          // [256*200]
    const float4* __restrict__ tok_tab,   // [VOCAB,32] rows 512B-aligned
    const float4* __restrict__ gen_tab,   // [21,32]
    const float4* __restrict__ pos_tab,   // [200,32]
    const int4* __restrict__ tgid,        // [VOCAB,8] as [VOCAB,2] int4
    const int* __restrict__ gcnt,         // [VOCAB]
    float4* __restrict__ out)             // [256*200,32]
{
    __shared__ alignas(128) float4 s_rows[TOK_PER_CTA * 32];  // 32 KB
    __shared__ int s_t[TOK_PER_CTA];
    __shared__ alignas(8) unsigned long long s_mbar;

    const int tid  = threadIdx.x;
    const int wid  = tid >> 5;
    const int lane = tid & 31;
    const int base = blockIdx.x * TOK_PER_CTA;

    const uint32_t mbar = smem_u32(&s_mbar);

    if (tid == 0) {
        asm volatile("mbarrier.init.shared.b64 [%0], 1;" :: "r"(mbar) : "memory");
    }
    // Load token ids (threads 0..63).
    if (tid < TOK_PER_CTA) s_t[tid] = __ldg(&seq[base + tid]);
    __syncthreads();

    // Post expected bytes, then fire 64 bulk row-gathers (threads 0..63).
    if (tid == 0) {
        asm volatile("mbarrier.arrive.expect_tx.shared.b64 _, [%0], %1;"
                     :: "r"(mbar), "r"(TILE_BYTES) : "memory");
    }
    __syncthreads();
    if (tid < TOK_PER_CTA) {
        const int t = s_t[tid];
        const uint32_t dst = smem_u32(&s_rows[tid * 32]);
        const float4* src = tok_tab + (size_t)t * 32;
        asm volatile(
            "cp.async.bulk.shared::cta.global.mbarrier::complete_tx::bytes "
            "[%0], [%1], %2, [%3];"
            :: "r"(dst), "l"(src), "r"(ROW_BYTES), "r"(mbar) : "memory");
    }

    // ---- Overlap: genre-mean + pos partials for this warp's 8 tokens ----
    float4 acc[8];
    #pragma unroll
    for (int k = 0; k < 8; k++) {
        const int j = wid * 8 + k;           // token within CTA
        const int t = s_t[j];                // warp-uniform LDS
        const int l = (base + j) % SEQ_L;

        const int  cnt = __ldg(&gcnt[t]);
        const int4 ga  = __ldg(&tgid[t * 2]);
        const int4 gb  = __ldg(&tgid[t * 2 + 1]);
        const float4 pos = __ldg(&pos_tab[l * 32 + lane]);
        const int gid[MAX_G] = {ga.x, ga.y, ga.z, ga.w, gb.x, gb.y, gb.z, gb.w};

        float4 s = make_float4(0.f, 0.f, 0.f, 0.f);
        #pragma unroll
        for (int g = 0; g < MAX_G; g++) {
            if (g < cnt) {
                const float4 ge = __ldg(&gen_tab[gid[g] * 32 + lane]);  // L1-hot
                s.x += ge.x; s.y += ge.y; s.z += ge.z; s.w += ge.w;
            }
        }
        const float inv = 1.0f / (float)cnt;
        acc[k].x = pos.x + s.x * inv;
        acc[k].y = pos.y + s.y * inv;
        acc[k].z = pos.z + s.z * inv;
        acc[k].w = pos.w + s.w * inv;
    }

    // ---- Wait for the bulk gathers, then add rows + stream out ----
    {
        unsigned done;
        asm volatile(
            "{\n\t"
            ".reg .pred p;\n\t"
            "WAIT_%=: mbarrier.try_wait.parity.shared.b64 p, [%1], %2, 0x989680;\n\t"
            "@!p bra WAIT_%=;\n\t"
            "mov.u32 %0, 1;\n\t"
            "}"
            : "=r"(done) : "r"(mbar), "r"(0) : "memory");
    }

    #pragma unroll
    for (int k = 0; k < 8; k++) {
        const int j = wid * 8 + k;
        const float4 tok = s_rows[j * 32 + lane];   // LDS.128, conflict-free
        float4 o;
        o.x = tok.x + acc[k].x;
        o.y = tok.y + acc[k].y;
        o.z = tok.z + acc[k].z;
        o.w = tok.w + acc[k].w;
        stg_cs(&out[(size_t)(base + j) * 32 + lane], o);
    }
}

extern "C" void kernel_launch(void* const* d_in, const int* in_sizes, int n_in,
                              void* d_out, int out_size) {
    const int*    seq     = (const int*)d_in[0];
    const float4* tok_tab = (const float4*)d_in[1];
    const float4* gen_tab = (const float4*)d_in[2];
    const float4* pos_tab = (const float4*)d_in[3];
    const int4*   tgid    = (const int4*)d_in[4];
    const int*    gcnt    = (const int*)d_in[5];
    float4*       out     = (float4*)d_out;

    bert_embed_kernel<<<GRID_BLOCKS, BLOCK_THREADS>>>(
        seq, tok_tab, gen_tab, pos_tab, tgid, gcnt, out);
}

// round 15
// speedup vs baseline: 1.2765x; 1.2765x over previous
#include <cuda_runtime.h>
#include <cstdint>

// BERTEmbedding: out[b,l,:] = token_table[seq[b,l],:]
//                           + mean_{g<cnt}(genre_table[gids[seq[b,l],g],:])
//                           + pos_table[l,:]
//
// R15 (final form): best measured configuration (R10, 14.816us x2) plus one
// micro-lever: the fp32 divide 1.0f/cnt (multi-instruction full-precision
// division sequence) is replaced by an exact constant reciprocal lookup
// (cnt in 1..8; table entries are the RN-rounded reciprocals, bitwise equal
// to what the divide produced).
//  - token-table gathers: ld.global.nc.L2::cache_hint (evict_last) — the only
//    lever that measurably beat the 15.07us plateau.
//  - output: st.global.cs (streaming, evict-first).
//  - warp per token, lane k owns float4 at dims [4k,4k+4); 6400x256.

#define NUM_TOKENS (256 * 200)
#define SEQ_L 200
#define MAX_G 8

__constant__ float c_inv[9] = {
    0.0f, 1.0f, 0.5f, 0.333333343f, 0.25f,
    0.2f, 0.166666672f, 0.142857149f, 0.125f
};

__device__ __forceinline__ uint64_t mk_evict_last_policy() {
    uint64_t pol;
    asm("createpolicy.fractional.L2::evict_last.b64 %0, 1.0;" : "=l"(pol));
    return pol;
}
__device__ __forceinline__ float4 ldg_hint(const float4* p, uint64_t pol) {
    float4 v;
    asm volatile("ld.global.nc.L2::cache_hint.v4.f32 {%0,%1,%2,%3}, [%4], %5;"
                 : "=f"(v.x), "=f"(v.y), "=f"(v.z), "=f"(v.w)
                 : "l"(p), "l"(pol));
    return v;
}
__device__ __forceinline__ void stg_cs(float4* p, float4 v) {
    asm volatile("st.global.cs.v4.f32 [%0], {%1,%2,%3,%4};"
                 :: "l"(p), "f"(v.x), "f"(v.y), "f"(v.z), "f"(v.w) : "memory");
}

__global__ __launch_bounds__(256) void bert_embed_kernel(
    const int* __restrict__ seq,          // [256*200]
    const float4* __restrict__ tok_tab,   // [VOCAB,32]
    const float4* __restrict__ gen_tab,   // [21,32]
    const float4* __restrict__ pos_tab,   // [200,32]
    const int4* __restrict__ tgid,        // [VOCAB,8] as [VOCAB,2] int4
    const int* __restrict__ gcnt,         // [VOCAB]
    float4* __restrict__ out)             // [256*200,32]
{
    const int warp = (blockIdx.x * blockDim.x + threadIdx.x) >> 5;
    const int lane = threadIdx.x & 31;

    const uint64_t pol = mk_evict_last_policy();

    const int l = warp % SEQ_L;
    const int t = __ldg(&seq[warp]);               // warp-uniform

    // Independent level-2 loads, back-to-back for MLP.
    const int    cnt = __ldg(&gcnt[t]);            // warp-uniform
    const int4   ga  = __ldg(&tgid[t * 2]);        // warp-uniform
    const int4   gb  = __ldg(&tgid[t * 2 + 1]);    // warp-uniform
    const float4 tok = ldg_hint(&tok_tab[(size_t)t * 32 + lane], pol);  // L2-pinned
    const float4 pos = __ldg(&pos_tab[l * 32 + lane]);

    const int gid[MAX_G] = {ga.x, ga.y, ga.z, ga.w, gb.x, gb.y, gb.z, gb.w};

    float4 s = make_float4(0.f, 0.f, 0.f, 0.f);
    #pragma unroll
    for (int g = 0; g < MAX_G; g++) {
        if (g < cnt) {                              // warp-uniform predicate
            const float4 ge = __ldg(&gen_tab[gid[g] * 32 + lane]);  // L1-hot
            s.x += ge.x; s.y += ge.y; s.z += ge.z; s.w += ge.w;
        }
    }

    const float inv = c_inv[cnt];                   // exact reciprocal, LDC
    float4 o;
    o.x = tok.x + pos.x + s.x * inv;
    o.y = tok.y + pos.y + s.y * inv;
    o.z = tok.z + pos.z + s.z * inv;
    o.w = tok.w + pos.w + s.w * inv;

    // Streaming store: evict-first, don't churn the table out of L2.
    stg_cs(&out[(size_t)warp * 32 + lane], o);
}

extern "C" void kernel_launch(void* const* d_in, const int* in_sizes, int n_in,
                              void* d_out, int out_size) {
    const int*    seq     = (const int*)d_in[0];
    const float4* tok_tab = (const float4*)d_in[1];
    const float4* gen_tab = (const float4*)d_in[2];
    const float4* pos_tab = (const float4*)d_in[3];
    const int4*   tgid    = (const int4*)d_in[4];
    const int*    gcnt    = (const int*)d_in[5];
    float4*       out     = (float4*)d_out;

    bert_embed_kernel<<<NUM_TOKENS / 8, 256>>>(
        seq, tok_tab, gen_tab, pos_tab, tgid, gcnt, out);
}